// round 16
// baseline (speedup 1.0000x reference)
#include <cuda_runtime.h>
#include <cuda_bf16.h>
#include <cuda_fp16.h>
#include <cstdint>

// ---------------------------------------------------------------------------
// GraphNetBlock, GB300 round 15 (mma.sync path; tcgen05 blocked by compute_103
// PTX target in the harness toolchain).
//   agg = segment_sum(edge_features, receivers)             (red.v4 atomics)
//   new_nodes = LN( [node_f, agg] @ Wn + bn )
//   P         = new_nodes @ [We_s | We_r]        (50k x 256, per-NODE)
//   new_edges = LN( ef @ We_e + P[s,0:128] + P[r,128:256] + be )
// R15: PERSISTENT CTAs for P/edge passes — B panel staged ONCE per CTA
//      (was once per 64-row tile: 150MB of L2 re-reads + 2 barriers/tile),
//      then a barrier-free grid-stride tile loop; gather indices loaded at
//      tile start so their latency hides under the mainloop.
// GEMMs: mma.sync m16n8k16 f16 single-term (rel_err 3.8e-4 << 1e-3 gate),
//        16x128 warp tile (L1 = LDG+LDS; warp reshapes proven losers twice).
// ---------------------------------------------------------------------------

#define NMAX 50000

static __device__ float g_agg[(size_t)NMAX * 128];
static __device__ float g_P[(size_t)NMAX * 256];
static __device__ __half g_nwT[128 * 256];   // node fused W^T, pitch 256
static __device__ __half g_PwT[256 * 128];   // [We_s|We_r]^T, pitch 128
static __device__ __half g_CwT[128 * 128];   // We_e^T, pitch 128
static __device__ float g_nbias[128];
static __device__ float g_ebias[128];

// --------------------------- weight prep -----------------------------------
__global__ void prep_weights_kernel(
    const float* __restrict__ nw1, const float* __restrict__ nb1,
    const float* __restrict__ nw2, const float* __restrict__ nb2,
    const float* __restrict__ ew1, const float* __restrict__ eb1,
    const float* __restrict__ ew2, const float* __restrict__ eb2)
{
    const int b = blockIdx.x;
    const int n = threadIdx.x;  // output column 0..127
    const float* row; const float* w2;
    __half* dh = nullptr;
    float* bd = nullptr;
    float extra = 0.0f;
    int pitch = 0, kk = 0, row_off = 0;
    if (b < 256) {
        row = nw1 + (size_t)b * 128; w2 = nw2;
        dh = g_nwT; pitch = 256; kk = b;
    } else if (b == 256) {
        row = nb1; w2 = nw2; bd = g_nbias; extra = nb2[n];
    } else if (b < 641) {
        int k = b - 257;           // 0..383 into edge W
        row = ew1 + (size_t)k * 128; w2 = ew2;
        if (k < 128)      { dh = g_PwT; pitch = 128; row_off = 0;   kk = k; }
        else if (k < 256) { dh = g_PwT; pitch = 128; row_off = 128; kk = k - 128; }
        else              { dh = g_CwT; pitch = 128; row_off = 0;   kk = k - 256; }
    } else {
        row = eb1; w2 = ew2; bd = g_ebias; extra = eb2[n];
    }
    float s = extra;
    #pragma unroll 4
    for (int j = 0; j < 128; j++)
        s = fmaf(row[j], w2[j * 128 + n], s);
    if (bd) {
        bd[n] = s;
    } else {
        dh[(size_t)(row_off + n) * pitch + kk] = __float2half_rn(s);
    }
}

// --------------------------- agg zero + scatter ----------------------------
__global__ void zero_agg_kernel(int n4)
{
    int i = blockIdx.x * blockDim.x + threadIdx.x;
    if (i < n4)
        reinterpret_cast<float4*>(g_agg)[i] = make_float4(0.f, 0.f, 0.f, 0.f);
}

__global__ void scatter_add_kernel(const float* __restrict__ ef,
                                   const int* __restrict__ recv, int E)
{
    long long t = (long long)blockIdx.x * blockDim.x + threadIdx.x;
    int e = (int)(t >> 5);
    if (e >= E) return;
    int c = (int)(t & 31);
    float4 v = __ldcs(reinterpret_cast<const float4*>(ef) + (size_t)e * 32 + c);
    float* dst = g_agg + (size_t)recv[e] * 128 + c * 4;
    asm volatile("red.global.add.v4.f32 [%0], {%1,%2,%3,%4};"
                 :: "l"(dst), "f"(v.x), "f"(v.y), "f"(v.z), "f"(v.w)
                 : "memory");
}

// --------------------------- mma helpers -----------------------------------
__device__ __forceinline__ void mma16816h(float c[4], const uint32_t a[4],
                                          uint32_t b0, uint32_t b1)
{
    asm volatile(
        "mma.sync.aligned.m16n8k16.row.col.f32.f16.f16.f32 "
        "{%0,%1,%2,%3}, {%4,%5,%6,%7}, {%8,%9}, {%0,%1,%2,%3};"
        : "+f"(c[0]), "+f"(c[1]), "+f"(c[2]), "+f"(c[3])
        : "r"(a[0]), "r"(a[1]), "r"(a[2]), "r"(a[3]), "r"(b0), "r"(b1));
}

__device__ __forceinline__ void ldsm4(uint32_t& r0, uint32_t& r1,
                                      uint32_t& r2, uint32_t& r3,
                                      const __half* p)
{
    uint32_t a = (uint32_t)__cvta_generic_to_shared(p);
    asm volatile("ldmatrix.sync.aligned.m8n8.x4.shared.b16 {%0,%1,%2,%3}, [%4];"
                 : "=r"(r0), "=r"(r1), "=r"(r2), "=r"(r3) : "r"(a));
}

__device__ __forceinline__ uint32_t cvt_h2(float2 v)
{
    __half2 h = __float22half2_rn(v);
    return *reinterpret_cast<uint32_t*>(&h);
}

#define BPITCH 136   // halves per SMEM B row; 272B stride = 4 banks mod 32

// --------------------------- fused GEMM kernels ----------------------------
// MODE 0: node pass (1 tile/CTA, 2 segments w/ restage).
//         seg0: A=node_f, B=Wn[:,0:128]; seg1: A=g_agg, B=Wn[:,128:256].
//         epi: +nbias, LN -> out.
// MODE 1: P pass, PERSISTENT. A=new_nodes, B=PwT col-block (blockIdx.y).
//         B staged once; barrier-free tile loop. epi: store g_P (pitch 256).
// MODE 2: edge pass, PERSISTENT. A=edge_f, B=CwT. B staged once; barrier-free
//         tile loop; gather indices loaded at tile start.
//         epi: + g_P[s,0:128] + g_P[r,128:256] + ebias, LN -> out.
// CTA = 128 threads (4 warps), tile 64 rows x 128 cols; warp w rows w*16..+15.
template<int MODE>
__global__ __launch_bounds__(128, 4) void mlp_ln_kernel(
    const float* __restrict__ xA,
    const int* __restrict__ senders,
    const int* __restrict__ receivers,
    const float* __restrict__ ln_g,
    const float* __restrict__ ln_b,
    float* __restrict__ out, int M, int ntiles)
{
    __shared__ __half SB[128 * BPITCH];
    __shared__ float s_bias[128], s_g[128], s_b[128];

    const int tid = threadIdx.x;
    const int warp = tid >> 5, lane = tid & 31;
    const int g = lane >> 2, q = lane & 3;
    const int laneRow = ((lane >> 4) << 3) + (lane & 7);
    const int laneK = ((lane >> 3) & 1) << 3;

    if (MODE != 1) {
        s_bias[tid] = MODE ? g_ebias[tid] : g_nbias[tid];
        s_g[tid] = ln_g[tid];
        s_b[tid] = ln_b[tid];
    }

    const __half* W;
    int wpitch;
    int ncol0 = 0;
    if (MODE == 0) { W = g_nwT; wpitch = 256; }
    else if (MODE == 1) {
        ncol0 = blockIdx.y * 128;
        W = g_PwT + (size_t)ncol0 * 128;
        wpitch = 128;
    } else { W = g_CwT; wpitch = 128; }

    // staging geometry: thread handles row n = tid>>4 (+8 per iter), int4 j
    const int st_n = tid >> 4;
    const int st_j = tid & 15;

    // MODE 1/2: stage the (tile-invariant) B panel ONCE per CTA.
    if (MODE != 0) {
        #pragma unroll
        for (int i = 0; i < 16; i++) {
            const int n = st_n + i * 8;
            reinterpret_cast<int4*>(SB + n * BPITCH)[st_j] =
                *reinterpret_cast<const int4*>(W + (size_t)n * wpitch + st_j * 8);
        }
        __syncthreads();
    }

    // -------- persistent tile loop (MODE 0 runs exactly once per CTA) ------
    for (int tile = blockIdx.x; tile < ntiles; tile += gridDim.x) {
        const int row0 = tile * 64 + warp * 16 + g;
        const int row1 = row0 + 8;
        const int r0c = min(row0, M - 1);
        const int r1c = min(row1, M - 1);

        // MODE 2: issue gather-index loads NOW; latency hides under mainloop.
        int s0, s1, d0, d1;
        if (MODE == 2) {
            s0 = senders[r0c];
            s1 = senders[r1c];
            d0 = receivers[r0c];
            d1 = receivers[r1c];
        }

        float acc[16][4];
        #pragma unroll
        for (int i = 0; i < 16; i++) {
            acc[i][0] = 0.f; acc[i][1] = 0.f; acc[i][2] = 0.f; acc[i][3] = 0.f;
        }

        const int NSEG = (MODE == 0) ? 2 : 1;
        #pragma unroll
        for (int seg = 0; seg < NSEG; seg++) {
            if (MODE == 0) {
                // restage this segment's B panel
                __syncthreads();
                #pragma unroll
                for (int i = 0; i < 16; i++) {
                    const int n = st_n + i * 8;
                    reinterpret_cast<int4*>(SB + n * BPITCH)[st_j] =
                        *reinterpret_cast<const int4*>(
                            W + (size_t)n * wpitch + seg * 128 + st_j * 8);
                }
                __syncthreads();
            }

            const float* base = (MODE == 0) ? ((seg == 0) ? xA : g_agg) : xA;
            const float* pa = base + (size_t)r0c * 128;
            const float* pb = base + (size_t)r1c * 128;

            // prefetch A for ks=0
            float2 x00, x10, x01, x11;
            {
                const int c0 = q * 2;
                if (MODE == 2) {
                    x00 = __ldcs(reinterpret_cast<const float2*>(pa + c0));
                    x10 = __ldcs(reinterpret_cast<const float2*>(pb + c0));
                    x01 = __ldcs(reinterpret_cast<const float2*>(pa + c0 + 8));
                    x11 = __ldcs(reinterpret_cast<const float2*>(pb + c0 + 8));
                } else {
                    x00 = *reinterpret_cast<const float2*>(pa + c0);
                    x10 = *reinterpret_cast<const float2*>(pb + c0);
                    x01 = *reinterpret_cast<const float2*>(pa + c0 + 8);
                    x11 = *reinterpret_cast<const float2*>(pb + c0 + 8);
                }
            }

            // ---- 8 barrier-free k-steps ----
            #pragma unroll 1
            for (int ks = 0; ks < 8; ks++) {
                uint32_t ah[4];
                ah[0] = cvt_h2(x00);
                ah[1] = cvt_h2(x10);
                ah[2] = cvt_h2(x01);
                ah[3] = cvt_h2(x11);

                // prefetch A for ks+1 (overlaps the mma chain below)
                if (ks < 7) {
                    const int c1 = (ks + 1) * 16 + q * 2;
                    if (MODE == 2) {
                        x00 = __ldcs(reinterpret_cast<const float2*>(pa + c1));
                        x10 = __ldcs(reinterpret_cast<const float2*>(pb + c1));
                        x01 = __ldcs(reinterpret_cast<const float2*>(pa + c1 + 8));
                        x11 = __ldcs(reinterpret_cast<const float2*>(pb + c1 + 8));
                    } else {
                        x00 = *reinterpret_cast<const float2*>(pa + c1);
                        x10 = *reinterpret_cast<const float2*>(pb + c1);
                        x01 = *reinterpret_cast<const float2*>(pa + c1 + 8);
                        x11 = *reinterpret_cast<const float2*>(pb + c1 + 8);
                    }
                }

                const int kcol = ks * 16 + laneK;
                // Groups of 4 n-tiles: 4 LDSM then 8 independent-acc MMAs.
                #pragma unroll
                for (int grp = 0; grp < 2; grp++) {
                    uint32_t bh[4][4];
                    #pragma unroll
                    for (int j = 0; j < 4; j++) {
                        const int srow = (grp * 4 + j) * 16 + laneRow;
                        ldsm4(bh[j][0], bh[j][1], bh[j][2], bh[j][3],
                              SB + srow * BPITCH + kcol);
                    }
                    #pragma unroll
                    for (int j = 0; j < 4; j++) {
                        mma16816h(acc[2 * (grp * 4 + j)],     ah, bh[j][0], bh[j][1]);
                        mma16816h(acc[2 * (grp * 4 + j) + 1], ah, bh[j][2], bh[j][3]);
                    }
                }
            }
        }

        // ---------------- epilogues ---------------------------------------
        if (MODE == 1) {
            if (row0 < M) {
                float* o = g_P + (size_t)row0 * 256 + ncol0;
                #pragma unroll
                for (int nt = 0; nt < 16; nt++) {
                    const int c = nt * 8 + q * 2;
                    *reinterpret_cast<float2*>(o + c) =
                        make_float2(acc[nt][0], acc[nt][1]);
                }
            }
            if (row1 < M) {
                float* o = g_P + (size_t)row1 * 256 + ncol0;
                #pragma unroll
                for (int nt = 0; nt < 16; nt++) {
                    const int c = nt * 8 + q * 2;
                    *reinterpret_cast<float2*>(o + c) =
                        make_float2(acc[nt][2], acc[nt][3]);
                }
            }
            continue;
        }

        if (MODE == 2) {
            const float* Ps0 = g_P + (size_t)s0 * 256;
            const float* Ps1 = g_P + (size_t)s1 * 256;
            const float* Pd0 = g_P + (size_t)d0 * 256 + 128;
            const float* Pd1 = g_P + (size_t)d1 * 256 + 128;
            #pragma unroll
            for (int nt = 0; nt < 16; nt++) {
                const int c = nt * 8 + q * 2;
                float2 a0 = *reinterpret_cast<const float2*>(Ps0 + c);
                float2 b0 = *reinterpret_cast<const float2*>(Pd0 + c);
                float2 a1 = *reinterpret_cast<const float2*>(Ps1 + c);
                float2 b1 = *reinterpret_cast<const float2*>(Pd1 + c);
                acc[nt][0] += a0.x + b0.x;
                acc[nt][1] += a0.y + b0.y;
                acc[nt][2] += a1.x + b1.x;
                acc[nt][3] += a1.y + b1.y;
            }
        }

        // bias + layernorm + store (MODE 0 and 2)
        float sum0 = 0.f, sq0 = 0.f, sum1 = 0.f, sq1 = 0.f;
        #pragma unroll
        for (int nt = 0; nt < 16; nt++) {
            const int c = nt * 8 + q * 2;
            const float b0 = s_bias[c], b1 = s_bias[c + 1];
            float v0 = acc[nt][0] + b0, v1 = acc[nt][1] + b1;
            float v2 = acc[nt][2] + b0, v3 = acc[nt][3] + b1;
            acc[nt][0] = v0; acc[nt][1] = v1; acc[nt][2] = v2; acc[nt][3] = v3;
            sum0 += v0 + v1; sq0 += v0 * v0 + v1 * v1;
            sum1 += v2 + v3; sq1 += v2 * v2 + v3 * v3;
        }
        #pragma unroll
        for (int m = 1; m <= 2; m <<= 1) {
            sum0 += __shfl_xor_sync(0xffffffffu, sum0, m);
            sq0  += __shfl_xor_sync(0xffffffffu, sq0, m);
            sum1 += __shfl_xor_sync(0xffffffffu, sum1, m);
            sq1  += __shfl_xor_sync(0xffffffffu, sq1, m);
        }
        const float inv = 1.0f / 128.0f;
        const float mu0 = sum0 * inv, mu1 = sum1 * inv;
        const float rs0 = rsqrtf(fmaxf(sq0 * inv - mu0 * mu0, 0.f) + 1e-5f);
        const float rs1 = rsqrtf(fmaxf(sq1 * inv - mu1 * mu1, 0.f) + 1e-5f);

        if (row0 < M) {
            float* o = out + (size_t)row0 * 128;
            #pragma unroll
            for (int nt = 0; nt < 16; nt++) {
                const int c = nt * 8 + q * 2;
                float2 w;
                w.x = (acc[nt][0] - mu0) * rs0 * s_g[c] + s_b[c];
                w.y = (acc[nt][1] - mu0) * rs0 * s_g[c + 1] + s_b[c + 1];
                *reinterpret_cast<float2*>(o + c) = w;
            }
        }
        if (row1 < M) {
            float* o = out + (size_t)row1 * 128;
            #pragma unroll
            for (int nt = 0; nt < 16; nt++) {
                const int c = nt * 8 + q * 2;
                float2 w;
                w.x = (acc[nt][2] - mu1) * rs1 * s_g[c] + s_b[c];
                w.y = (acc[nt][3] - mu1) * rs1 * s_g[c + 1] + s_b[c + 1];
                *reinterpret_cast<float2*>(o + c) = w;
            }
        }
    }
}

// ---------------------------------------------------------------------------
extern "C" void kernel_launch(void* const* d_in, const int* in_sizes, int n_in,
                              void* d_out, int out_size)
{
    const float* node_f   = (const float*)d_in[0];
    const float* edge_f   = (const float*)d_in[1];
    const int*   senders  = (const int*)d_in[2];
    const int*   receivers= (const int*)d_in[3];
    const float* nw1 = (const float*)d_in[4];
    const float* nb1 = (const float*)d_in[5];
    const float* nw2 = (const float*)d_in[6];
    const float* nb2 = (const float*)d_in[7];
    const float* nlg = (const float*)d_in[8];
    const float* nlb = (const float*)d_in[9];
    const float* ew1 = (const float*)d_in[10];
    const float* eb1 = (const float*)d_in[11];
    const float* ew2 = (const float*)d_in[12];
    const float* eb2 = (const float*)d_in[13];
    const float* elg = (const float*)d_in[14];
    const float* elb = (const float*)d_in[15];

    const int N = in_sizes[0] / 128;   // 50000
    const int E = in_sizes[2];         // 300000

    float* out_nodes = (float*)d_out;
    float* out_edges = out_nodes + (size_t)N * 128;

    const int ntiles_n = (N + 63) / 64;   // 782
    const int ntiles_e = (E + 63) / 64;   // 4688

    // 1) fuse W1@W2 (+ bias), transpose, convert to fp16
    prep_weights_kernel<<<642, 128>>>(nw1, nb1, nw2, nb2, ew1, eb1, ew2, eb2);

    // 2) agg = segment_sum(edge_features, receivers)
    zero_agg_kernel<<<(N * 32 + 255) / 256, 256>>>(N * 32);
    {
        long long threads = (long long)E * 32;
        int grid = (int)((threads + 255) / 256);
        scatter_add_kernel<<<grid, 256>>>(edge_f, receivers, E);
    }

    // 3) node pass: LN(node_f@Wn_top + agg@Wn_bot + bn) -> out_nodes
    mlp_ln_kernel<0><<<ntiles_n, 128>>>(
        node_f, nullptr, nullptr, nlg, nlb, out_nodes, N, ntiles_n);

    // 4) P pass (persistent): P = new_nodes @ [We_s|We_r] -> g_P (50k x 256)
    {
        dim3 grid(296, 2);
        mlp_ln_kernel<1><<<grid, 128>>>(
            out_nodes, nullptr, nullptr, nullptr, nullptr, nullptr, N, ntiles_n);
    }

    // 5) edge pass (persistent):
    //    LN(ef @ We_e + P[s,0:128] + P[r,128:256] + be) -> out_edges
    mlp_ln_kernel<2><<<592, 128>>>(
        edge_f, senders, receivers, elg, elb, out_edges, E, ntiles_e);
}

// round 17
// speedup vs baseline: 1.3901x; 1.3901x over previous
#include <cuda_runtime.h>
#include <cuda_bf16.h>
#include <cuda_fp16.h>
#include <cstdint>

// ---------------------------------------------------------------------------
// GraphNetBlock, GB300 round 16 = R14 (best: 239.6us) + low-risk tweaks.
//   agg = segment_sum(edge_features, receivers)             (red.v4 atomics)
//   new_nodes = LN( [node_f, agg] @ Wn + bn )
//   P         = new_nodes @ [We_s | We_r]        (50k x 256, per-NODE)
//   new_edges = LN( ef @ We_e + P[s,0:128] + P[r,128:256] + be )
// R16: revert R15 persistence (big loss: oversubscription IS the latency
//      hiding for these tiles). Tweaks vs R14: (1) gather indices loaded at
//      tile START in edge pass; (2) out_edges stored with st.cs to keep the
//      P table L2-resident.
// GEMMs: mma.sync m16n8k16 f16 single-term (rel_err 3.8e-4 << 1e-3 gate),
//        16x128 warp tile, full-K B panel, 8 barrier-free k-steps/segment.
// ---------------------------------------------------------------------------

#define NMAX 50000

static __device__ float g_agg[(size_t)NMAX * 128];
static __device__ float g_P[(size_t)NMAX * 256];
static __device__ __half g_nwT[128 * 256];   // node fused W^T, pitch 256
static __device__ __half g_PwT[256 * 128];   // [We_s|We_r]^T, pitch 128
static __device__ __half g_CwT[128 * 128];   // We_e^T, pitch 128
static __device__ float g_nbias[128];
static __device__ float g_ebias[128];

// --------------------------- weight prep -----------------------------------
__global__ void prep_weights_kernel(
    const float* __restrict__ nw1, const float* __restrict__ nb1,
    const float* __restrict__ nw2, const float* __restrict__ nb2,
    const float* __restrict__ ew1, const float* __restrict__ eb1,
    const float* __restrict__ ew2, const float* __restrict__ eb2)
{
    const int b = blockIdx.x;
    const int n = threadIdx.x;  // output column 0..127
    const float* row; const float* w2;
    __half* dh = nullptr;
    float* bd = nullptr;
    float extra = 0.0f;
    int pitch = 0, kk = 0, row_off = 0;
    if (b < 256) {
        row = nw1 + (size_t)b * 128; w2 = nw2;
        dh = g_nwT; pitch = 256; kk = b;
    } else if (b == 256) {
        row = nb1; w2 = nw2; bd = g_nbias; extra = nb2[n];
    } else if (b < 641) {
        int k = b - 257;           // 0..383 into edge W
        row = ew1 + (size_t)k * 128; w2 = ew2;
        if (k < 128)      { dh = g_PwT; pitch = 128; row_off = 0;   kk = k; }
        else if (k < 256) { dh = g_PwT; pitch = 128; row_off = 128; kk = k - 128; }
        else              { dh = g_CwT; pitch = 128; row_off = 0;   kk = k - 256; }
    } else {
        row = eb1; w2 = ew2; bd = g_ebias; extra = eb2[n];
    }
    float s = extra;
    #pragma unroll 4
    for (int j = 0; j < 128; j++)
        s = fmaf(row[j], w2[j * 128 + n], s);
    if (bd) {
        bd[n] = s;
    } else {
        dh[(size_t)(row_off + n) * pitch + kk] = __float2half_rn(s);
    }
}

// --------------------------- agg zero + scatter ----------------------------
__global__ void zero_agg_kernel(int n4)
{
    int i = blockIdx.x * blockDim.x + threadIdx.x;
    if (i < n4)
        reinterpret_cast<float4*>(g_agg)[i] = make_float4(0.f, 0.f, 0.f, 0.f);
}

__global__ void scatter_add_kernel(const float* __restrict__ ef,
                                   const int* __restrict__ recv, int E)
{
    long long t = (long long)blockIdx.x * blockDim.x + threadIdx.x;
    int e = (int)(t >> 5);
    if (e >= E) return;
    int c = (int)(t & 31);
    float4 v = __ldcs(reinterpret_cast<const float4*>(ef) + (size_t)e * 32 + c);
    float* dst = g_agg + (size_t)recv[e] * 128 + c * 4;
    asm volatile("red.global.add.v4.f32 [%0], {%1,%2,%3,%4};"
                 :: "l"(dst), "f"(v.x), "f"(v.y), "f"(v.z), "f"(v.w)
                 : "memory");
}

// --------------------------- mma helpers -----------------------------------
__device__ __forceinline__ void mma16816h(float c[4], const uint32_t a[4],
                                          uint32_t b0, uint32_t b1)
{
    asm volatile(
        "mma.sync.aligned.m16n8k16.row.col.f32.f16.f16.f32 "
        "{%0,%1,%2,%3}, {%4,%5,%6,%7}, {%8,%9}, {%0,%1,%2,%3};"
        : "+f"(c[0]), "+f"(c[1]), "+f"(c[2]), "+f"(c[3])
        : "r"(a[0]), "r"(a[1]), "r"(a[2]), "r"(a[3]), "r"(b0), "r"(b1));
}

__device__ __forceinline__ void ldsm4(uint32_t& r0, uint32_t& r1,
                                      uint32_t& r2, uint32_t& r3,
                                      const __half* p)
{
    uint32_t a = (uint32_t)__cvta_generic_to_shared(p);
    asm volatile("ldmatrix.sync.aligned.m8n8.x4.shared.b16 {%0,%1,%2,%3}, [%4];"
                 : "=r"(r0), "=r"(r1), "=r"(r2), "=r"(r3) : "r"(a));
}

__device__ __forceinline__ uint32_t cvt_h2(float2 v)
{
    __half2 h = __float22half2_rn(v);
    return *reinterpret_cast<uint32_t*>(&h);
}

__device__ __forceinline__ void stcs_f2(float* p, float2 v)
{
    asm volatile("st.global.cs.v2.f32 [%0], {%1,%2};"
                 :: "l"(p), "f"(v.x), "f"(v.y) : "memory");
}

#define BPITCH 136   // halves per SMEM B row; 272B stride = 4 banks mod 32

// --------------------------- fused GEMM kernels ----------------------------
// MODE 0: node pass, NSEG=2. seg0: A=node_f, B=Wn[:,0:128];
//                            seg1: A=g_agg,  B=Wn[:,128:256]. +nbias, LN.
// MODE 1: P pass, NSEG=1.    A=new_nodes, B=PwT col-block (blockIdx.y).
// MODE 2: edge pass, NSEG=1. A=edge_f, B=CwT; indices loaded at tile start;
//         epi + P gathers + ebias, LN, st.cs -> out.
// CTA = 128 threads (4 warps), tile 64 rows x 128 cols; warp w rows w*16..+15.
// Per segment: stage full 128-K B panel once, then 8 barrier-free k-steps.
template<int MODE, int NSEG>
__global__ __launch_bounds__(128, 4) void mlp_ln_kernel(
    const float* __restrict__ xA,
    const int* __restrict__ senders,
    const int* __restrict__ receivers,
    const float* __restrict__ ln_g,
    const float* __restrict__ ln_b,
    float* __restrict__ out, int M)
{
    __shared__ __half SB[128 * BPITCH];
    __shared__ float s_bias[128], s_g[128], s_b[128];

    const int tid = threadIdx.x;
    const int warp = tid >> 5, lane = tid & 31;
    const int g = lane >> 2, q = lane & 3;
    const int laneRow = ((lane >> 4) << 3) + (lane & 7);
    const int laneK = ((lane >> 3) & 1) << 3;

    if (MODE != 1) {
        s_bias[tid] = MODE ? g_ebias[tid] : g_nbias[tid];
        s_g[tid] = ln_g[tid];
        s_b[tid] = ln_b[tid];
    }

    const int row0 = blockIdx.x * 64 + warp * 16 + g;
    const int row1 = row0 + 8;
    const int r0c = min(row0, M - 1);
    const int r1c = min(row1, M - 1);

    // MODE 2: issue gather-index loads NOW; latency hides under stage+mainloop
    int s0, s1, d0, d1;
    if (MODE == 2) {
        s0 = senders[r0c];
        s1 = senders[r1c];
        d0 = receivers[r0c];
        d1 = receivers[r1c];
    }

    const __half* W;
    int wpitch;
    int ncol0 = 0;
    if (MODE == 0) { W = g_nwT; wpitch = 256; }
    else if (MODE == 1) {
        ncol0 = blockIdx.y * 128;
        W = g_PwT + (size_t)ncol0 * 128;
        wpitch = 128;
    } else { W = g_CwT; wpitch = 128; }

    // staging geometry: thread handles row n = tid>>4 (+8 per iter), int4 j
    const int st_n = tid >> 4;
    const int st_j = tid & 15;

    float acc[16][4];
    #pragma unroll
    for (int i = 0; i < 16; i++) {
        acc[i][0] = 0.f; acc[i][1] = 0.f; acc[i][2] = 0.f; acc[i][3] = 0.f;
    }

    #pragma unroll
    for (int seg = 0; seg < NSEG; seg++) {
        // ---- stage full 128-K B panel for this segment ----
        if (seg > 0) __syncthreads();        // prior segment's reads done
        #pragma unroll
        for (int i = 0; i < 16; i++) {
            const int n = st_n + i * 8;
            reinterpret_cast<int4*>(SB + n * BPITCH)[st_j] =
                *reinterpret_cast<const int4*>(
                    W + (size_t)n * wpitch + seg * 128 + st_j * 8);
        }
        __syncthreads();

        const float* base = (MODE == 0) ? ((seg == 0) ? xA : g_agg) : xA;
        const float* pa = base + (size_t)r0c * 128;
        const float* pb = base + (size_t)r1c * 128;

        // prefetch A for ks=0
        float2 x00, x10, x01, x11;
        {
            const int c0 = q * 2;
            if (MODE == 2) {
                x00 = __ldcs(reinterpret_cast<const float2*>(pa + c0));
                x10 = __ldcs(reinterpret_cast<const float2*>(pb + c0));
                x01 = __ldcs(reinterpret_cast<const float2*>(pa + c0 + 8));
                x11 = __ldcs(reinterpret_cast<const float2*>(pb + c0 + 8));
            } else {
                x00 = *reinterpret_cast<const float2*>(pa + c0);
                x10 = *reinterpret_cast<const float2*>(pb + c0);
                x01 = *reinterpret_cast<const float2*>(pa + c0 + 8);
                x11 = *reinterpret_cast<const float2*>(pb + c0 + 8);
            }
        }

        // ---- 8 barrier-free k-steps ----
        #pragma unroll 1
        for (int ks = 0; ks < 8; ks++) {
            uint32_t ah[4];
            ah[0] = cvt_h2(x00);
            ah[1] = cvt_h2(x10);
            ah[2] = cvt_h2(x01);
            ah[3] = cvt_h2(x11);

            // prefetch A for ks+1 (overlaps the mma chain below)
            if (ks < 7) {
                const int c1 = (ks + 1) * 16 + q * 2;
                if (MODE == 2) {
                    x00 = __ldcs(reinterpret_cast<const float2*>(pa + c1));
                    x10 = __ldcs(reinterpret_cast<const float2*>(pb + c1));
                    x01 = __ldcs(reinterpret_cast<const float2*>(pa + c1 + 8));
                    x11 = __ldcs(reinterpret_cast<const float2*>(pb + c1 + 8));
                } else {
                    x00 = *reinterpret_cast<const float2*>(pa + c1);
                    x10 = *reinterpret_cast<const float2*>(pb + c1);
                    x01 = *reinterpret_cast<const float2*>(pa + c1 + 8);
                    x11 = *reinterpret_cast<const float2*>(pb + c1 + 8);
                }
            }

            const int kcol = ks * 16 + laneK;
            // Groups of 4 n-tiles: 4 LDSM then 8 independent-acc MMAs.
            #pragma unroll
            for (int grp = 0; grp < 2; grp++) {
                uint32_t bh[4][4];
                #pragma unroll
                for (int j = 0; j < 4; j++) {
                    const int srow = (grp * 4 + j) * 16 + laneRow;
                    ldsm4(bh[j][0], bh[j][1], bh[j][2], bh[j][3],
                          SB + srow * BPITCH + kcol);
                }
                #pragma unroll
                for (int j = 0; j < 4; j++) {
                    mma16816h(acc[2 * (grp * 4 + j)],     ah, bh[j][0], bh[j][1]);
                    mma16816h(acc[2 * (grp * 4 + j) + 1], ah, bh[j][2], bh[j][3]);
                }
            }
        }
    }

    // ---------------- epilogues -------------------------------------------
    if (MODE == 1) {
        if (row0 < M) {
            float* o = g_P + (size_t)row0 * 256 + ncol0;
            #pragma unroll
            for (int nt = 0; nt < 16; nt++) {
                const int c = nt * 8 + q * 2;
                *reinterpret_cast<float2*>(o + c) = make_float2(acc[nt][0], acc[nt][1]);
            }
        }
        if (row1 < M) {
            float* o = g_P + (size_t)row1 * 256 + ncol0;
            #pragma unroll
            for (int nt = 0; nt < 16; nt++) {
                const int c = nt * 8 + q * 2;
                *reinterpret_cast<float2*>(o + c) = make_float2(acc[nt][2], acc[nt][3]);
            }
        }
        return;
    }

    if (MODE == 2) {
        const float* Ps0 = g_P + (size_t)s0 * 256;
        const float* Ps1 = g_P + (size_t)s1 * 256;
        const float* Pd0 = g_P + (size_t)d0 * 256 + 128;
        const float* Pd1 = g_P + (size_t)d1 * 256 + 128;
        #pragma unroll
        for (int nt = 0; nt < 16; nt++) {
            const int c = nt * 8 + q * 2;
            float2 a0 = *reinterpret_cast<const float2*>(Ps0 + c);
            float2 b0 = *reinterpret_cast<const float2*>(Pd0 + c);
            float2 a1 = *reinterpret_cast<const float2*>(Ps1 + c);
            float2 b1 = *reinterpret_cast<const float2*>(Pd1 + c);
            acc[nt][0] += a0.x + b0.x;
            acc[nt][1] += a0.y + b0.y;
            acc[nt][2] += a1.x + b1.x;
            acc[nt][3] += a1.y + b1.y;
        }
    }

    // bias + layernorm + store (MODE 0 and 2)
    float sum0 = 0.f, sq0 = 0.f, sum1 = 0.f, sq1 = 0.f;
    #pragma unroll
    for (int nt = 0; nt < 16; nt++) {
        const int c = nt * 8 + q * 2;
        const float b0 = s_bias[c], b1 = s_bias[c + 1];
        float v0 = acc[nt][0] + b0, v1 = acc[nt][1] + b1;
        float v2 = acc[nt][2] + b0, v3 = acc[nt][3] + b1;
        acc[nt][0] = v0; acc[nt][1] = v1; acc[nt][2] = v2; acc[nt][3] = v3;
        sum0 += v0 + v1; sq0 += v0 * v0 + v1 * v1;
        sum1 += v2 + v3; sq1 += v2 * v2 + v3 * v3;
    }
    #pragma unroll
    for (int m = 1; m <= 2; m <<= 1) {
        sum0 += __shfl_xor_sync(0xffffffffu, sum0, m);
        sq0  += __shfl_xor_sync(0xffffffffu, sq0, m);
        sum1 += __shfl_xor_sync(0xffffffffu, sum1, m);
        sq1  += __shfl_xor_sync(0xffffffffu, sq1, m);
    }
    const float inv = 1.0f / 128.0f;
    const float mu0 = sum0 * inv, mu1 = sum1 * inv;
    const float rs0 = rsqrtf(fmaxf(sq0 * inv - mu0 * mu0, 0.f) + 1e-5f);
    const float rs1 = rsqrtf(fmaxf(sq1 * inv - mu1 * mu1, 0.f) + 1e-5f);

    if (row0 < M) {
        float* o = out + (size_t)row0 * 128;
        #pragma unroll
        for (int nt = 0; nt < 16; nt++) {
            const int c = nt * 8 + q * 2;
            float2 w;
            w.x = (acc[nt][0] - mu0) * rs0 * s_g[c] + s_b[c];
            w.y = (acc[nt][1] - mu0) * rs0 * s_g[c + 1] + s_b[c + 1];
            if (MODE == 2) stcs_f2(o + c, w);
            else *reinterpret_cast<float2*>(o + c) = w;
        }
    }
    if (row1 < M) {
        float* o = out + (size_t)row1 * 128;
        #pragma unroll
        for (int nt = 0; nt < 16; nt++) {
            const int c = nt * 8 + q * 2;
            float2 w;
            w.x = (acc[nt][2] - mu1) * rs1 * s_g[c] + s_b[c];
            w.y = (acc[nt][3] - mu1) * rs1 * s_g[c + 1] + s_b[c + 1];
            if (MODE == 2) stcs_f2(o + c, w);
            else *reinterpret_cast<float2*>(o + c) = w;
        }
    }
}

// ---------------------------------------------------------------------------
extern "C" void kernel_launch(void* const* d_in, const int* in_sizes, int n_in,
                              void* d_out, int out_size)
{
    const float* node_f   = (const float*)d_in[0];
    const float* edge_f   = (const float*)d_in[1];
    const int*   senders  = (const int*)d_in[2];
    const int*   receivers= (const int*)d_in[3];
    const float* nw1 = (const float*)d_in[4];
    const float* nb1 = (const float*)d_in[5];
    const float* nw2 = (const float*)d_in[6];
    const float* nb2 = (const float*)d_in[7];
    const float* nlg = (const float*)d_in[8];
    const float* nlb = (const float*)d_in[9];
    const float* ew1 = (const float*)d_in[10];
    const float* eb1 = (const float*)d_in[11];
    const float* ew2 = (const float*)d_in[12];
    const float* eb2 = (const float*)d_in[13];
    const float* elg = (const float*)d_in[14];
    const float* elb = (const float*)d_in[15];

    const int N = in_sizes[0] / 128;   // 50000
    const int E = in_sizes[2];         // 300000

    float* out_nodes = (float*)d_out;
    float* out_edges = out_nodes + (size_t)N * 128;

    // 1) fuse W1@W2 (+ bias), transpose, convert to fp16
    prep_weights_kernel<<<642, 128>>>(nw1, nb1, nw2, nb2, ew1, eb1, ew2, eb2);

    // 2) agg = segment_sum(edge_features, receivers)
    zero_agg_kernel<<<(N * 32 + 255) / 256, 256>>>(N * 32);
    {
        long long threads = (long long)E * 32;
        int grid = (int)((threads + 255) / 256);
        scatter_add_kernel<<<grid, 256>>>(edge_f, receivers, E);
    }

    // 3) node pass: LN(node_f@Wn_top + agg@Wn_bot + bn) -> out_nodes
    mlp_ln_kernel<0, 2><<<(N + 63) / 64, 128>>>(
        node_f, nullptr, nullptr, nlg, nlb, out_nodes, N);

    // 4) P pass: P = new_nodes @ [We_s|We_r] -> g_P (50k x 256)
    {
        dim3 grid((N + 63) / 64, 2);
        mlp_ln_kernel<1, 1><<<grid, 128>>>(
            out_nodes, nullptr, nullptr, nullptr, nullptr, nullptr, N);
    }

    // 5) edge pass: LN(ef @ We_e + P[s,0:128] + P[r,128:256] + be) -> out_edges
    mlp_ln_kernel<2, 1><<<(E + 63) / 64, 128>>>(
        edge_f, senders, receivers, elg, elb, out_edges, E);
}